// round 2
// baseline (speedup 1.0000x reference)
#include <cuda_runtime.h>

// Sobel_16724602651101
// x: (16, 3, 512, 512) fp32
// out: [magnitude (16,512,512) | angle (16,512,512)] fp32, concatenated.
//
// Per-channel Sobel (kornia normalized, /8), replicate ("edge") padding,
// first-occurrence argmax over channels by per-channel magnitude, then
// magnitude = sqrt(gx^2+gy^2+1e-9), angle = clip(gx / (gy==0 ? 1e-9 : gy), -10, 10).

#define BATCH 16
#define CH 3
#define HH 512
#define WW 512

#define TILE 32          // output tile is TILE x TILE
#define TB (TILE + 2)    // 34: input tile incl. halo
#define PITCH 36         // smem row pitch (avoid pathological bank patterns)

__global__ __launch_bounds__(256, 4)
void sobel_kernel(const float* __restrict__ x, float* __restrict__ out)
{
    __shared__ float s[CH][TB][PITCH];

    const int bx = blockIdx.x * TILE;      // tile origin col
    const int by = blockIdx.y * TILE;      // tile origin row
    const int b  = blockIdx.z;             // batch
    const int tid = threadIdx.y * 32 + threadIdx.x;

    const float* __restrict__ xb = x + (size_t)b * CH * HH * WW;

    // Cooperative load of 3 channels x 34x34 halo tile, replicate-clamped.
    #pragma unroll 1
    for (int i = tid; i < CH * TB * TB; i += 256) {
        int c   = i / (TB * TB);
        int rem = i - c * (TB * TB);
        int r   = rem / TB;
        int col = rem - r * TB;
        int gr = by + r - 1;   gr = min(max(gr, 0), HH - 1);
        int gc = bx + col - 1; gc = min(max(gc, 0), WW - 1);
        s[c][r][col] = __ldg(xb + (size_t)c * HH * WW + (size_t)gr * WW + gc);
    }
    __syncthreads();

    const int tx = threadIdx.x;

    #pragma unroll
    for (int k = 0; k < 4; k++) {
        const int ly = threadIdx.y + k * 8;   // local output row 0..31

        float bgx = 0.f, bgy = 0.f, bmag = -1.f;

        #pragma unroll
        for (int c = 0; c < CH; c++) {
            // smem rows ly..ly+2, cols tx..tx+2 cover the 3x3 window
            float a00 = s[c][ly    ][tx    ];
            float a01 = s[c][ly    ][tx + 1];
            float a02 = s[c][ly    ][tx + 2];
            float a10 = s[c][ly + 1][tx    ];
            float a12 = s[c][ly + 1][tx + 2];
            float a20 = s[c][ly + 2][tx    ];
            float a21 = s[c][ly + 2][tx + 1];
            float a22 = s[c][ly + 2][tx + 2];

            // cross-correlation with gx=[[-1,0,1],[-2,0,2],[-1,0,1]]/8, gy = gx^T
            float gx = ((a02 - a00) + 2.0f * (a12 - a10) + (a22 - a20)) * 0.125f;
            float gy = ((a20 - a00) + 2.0f * (a21 - a01) + (a22 - a02)) * 0.125f;
            float mag = sqrtf(gx * gx + gy * gy + 1e-9f);

            // strict > keeps the FIRST channel on ties (jnp.argmax semantics)
            if (mag > bmag) { bmag = mag; bgx = gx; bgy = gy; }
        }

        float ytr = (bgy == 0.0f) ? 1e-9f : bgy;
        float ang = bgx / ytr;
        ang = fminf(fmaxf(ang, -10.0f), 10.0f);

        const size_t o = (size_t)b * HH * WW + (size_t)(by + ly) * WW + (bx + tx);
        out[o] = bmag;
        out[(size_t)BATCH * HH * WW + o] = ang;
    }
}

extern "C" void kernel_launch(void* const* d_in, const int* in_sizes, int n_in,
                              void* d_out, int out_size)
{
    const float* x = (const float*)d_in[0];
    float* out = (float*)d_out;

    dim3 block(32, 8, 1);
    dim3 grid(WW / TILE, HH / TILE, BATCH);   // (16, 16, 16)
    sobel_kernel<<<grid, block>>>(x, out);
}

// round 3
// speedup vs baseline: 1.4175x; 1.4175x over previous
#include <cuda_runtime.h>

// Sobel_16724602651101
// x: (16, 3, 512, 512) fp32
// out: [magnitude (16,512,512) | angle (16,512,512)] fp32 concatenated.
//
// R2: 32x64 tiles, register sliding window (9 LDS/pixel), float4 halo loads.
// Per-pixel arithmetic is IDENTICAL to the R1 kernel (matched XLA at 1e-7).

#define BATCH 16
#define CH 3
#define HH 512
#define WW 512
#define HW (HH * WW)

#define TW 32            // tile width  (output)
#define TH 64            // tile height (output)
#define HALO_H (TH + 2)  // 66 halo rows
#define SPITCH 40        // smem row pitch in floats (10 float4), 16B aligned
// local col j <-> global col (bx0 - 4 + j); compute window uses cols tx+3..tx+5

__global__ __launch_bounds__(256)
void sobel_kernel(const float* __restrict__ x, float* __restrict__ out)
{
    __shared__ float s[CH][HALO_H][SPITCH];

    const int bx0 = blockIdx.x * TW;
    const int by0 = blockIdx.y * TH;
    const int b   = blockIdx.z;
    const int tx  = threadIdx.x;
    const int tid = threadIdx.y * 32 + tx;

    const float* __restrict__ xb = x + (size_t)b * CH * HW;

    // interior-x iff all 40 loaded cols (bx0-4 .. bx0+35) are in [0,511]
    const bool interior = (bx0 >= 4) && (bx0 + 36 <= WW);

    if (interior) {
        #pragma unroll
        for (int c = 0; c < CH; c++) {
            const float* __restrict__ xc = xb + c * HW;
            #pragma unroll 1
            for (int i = tid; i < HALO_H * (SPITCH / 4); i += 256) {
                int r = i / (SPITCH / 4);
                int j = i - r * (SPITCH / 4);          // 0..9
                int gr = min(max(by0 - 1 + r, 0), HH - 1);
                float4 v = *(const float4*)(xc + (size_t)gr * WW + (bx0 - 4) + 4 * j);
                *(float4*)&s[c][r][4 * j] = v;
            }
        }
    } else {
        // x-edge blocks: scalar, replicate-clamped, only the needed cols 3..36
        #pragma unroll
        for (int c = 0; c < CH; c++) {
            const float* __restrict__ xc = xb + c * HW;
            #pragma unroll 1
            for (int i = tid; i < HALO_H * 34; i += 256) {
                int r = i / 34;
                int j = i - r * 34 + 3;                // 3..36
                int gr = min(max(by0 - 1 + r, 0), HH - 1);
                int gc = min(max(bx0 - 4 + j, 0), WW - 1);
                s[c][r][j] = __ldg(xc + (size_t)gr * WW + gc);
            }
        }
    }
    __syncthreads();

    // Each thread computes 8 consecutive output rows: halo rows r0 .. r0+9.
    const int r0 = threadIdx.y * 8;

    // Rolling raw-value window: 3 rows x 3 cols x 3 channels in registers.
    float A[CH][3], B[CH][3], C[CH][3];

    #define LROW(c, rr, sl)                 \
        A[c][sl] = s[c][rr][tx + 3];        \
        B[c][sl] = s[c][rr][tx + 4];        \
        C[c][sl] = s[c][rr][tx + 5];

    #pragma unroll
    for (int c = 0; c < CH; c++) {
        LROW(c, r0,     0)
        LROW(c, r0 + 1, 1)
    }

    const size_t obase = (size_t)b * HW + (size_t)(by0 + r0) * WW + (bx0 + tx);
    const size_t oang  = (size_t)BATCH * HW;

    #pragma unroll
    for (int k = 0; k < 8; k++) {
        const int sl0 = k % 3, sl1 = (k + 1) % 3, sl2 = (k + 2) % 3;

        #pragma unroll
        for (int c = 0; c < CH; c++) {
            LROW(c, r0 + k + 2, sl2)
        }

        float bgx = 0.f, bgy = 0.f, bmag = -1.f;

        #pragma unroll
        for (int c = 0; c < CH; c++) {
            float a00 = A[c][sl0], a01 = B[c][sl0], a02 = C[c][sl0];
            float a10 = A[c][sl1],                  a12 = C[c][sl1];
            float a20 = A[c][sl2], a21 = B[c][sl2], a22 = C[c][sl2];

            // identical expressions to the R1 kernel (matched XLA reference)
            float gx = ((a02 - a00) + 2.0f * (a12 - a10) + (a22 - a20)) * 0.125f;
            float gy = ((a20 - a00) + 2.0f * (a21 - a01) + (a22 - a02)) * 0.125f;
            float mag = sqrtf(gx * gx + gy * gy + 1e-9f);

            if (mag > bmag) { bmag = mag; bgx = gx; bgy = gy; }
        }

        float ytr = (bgy == 0.0f) ? 1e-9f : bgy;
        float ang = bgx / ytr;
        ang = fminf(fmaxf(ang, -10.0f), 10.0f);

        const size_t o = obase + (size_t)k * WW;
        out[o]        = bmag;
        out[oang + o] = ang;
    }
    #undef LROW
}

extern "C" void kernel_launch(void* const* d_in, const int* in_sizes, int n_in,
                              void* d_out, int out_size)
{
    const float* x = (const float*)d_in[0];
    float* out = (float*)d_out;

    dim3 block(32, 8, 1);
    dim3 grid(WW / TW, HH / TH, BATCH);   // (16, 8, 16) = 2048 blocks
    sobel_kernel<<<grid, block>>>(x, out);
}

// round 4
// speedup vs baseline: 1.4298x; 1.0087x over previous
#include <cuda_runtime.h>

// Sobel_16724602651101  — R3
// x: (16, 3, 512, 512) fp32 -> out: [magnitude | angle] each (16,512,512) fp32.
//
// 64x32 tiles, 2 pixels/thread in x (float2 LDS/STG), register sliding window,
// argmax over channels on m^2 (single sqrt), per-pixel fp expressions bitwise
// identical to the R1/R2 kernels (which matched XLA at 1.06e-7).

#define BATCH 16
#define CH 3
#define HH 512
#define WW 512
#define HW (HH * WW)

#define TW 64            // tile width  (output)
#define TH 32            // tile height (output)
#define HALO_H (TH + 2)  // 34 halo rows
#define SPITCH 72        // smem row pitch (18 float4); local col j = globalcol-(bx0-4)

__global__ __launch_bounds__(256)
void sobel_kernel(const float* __restrict__ x, float* __restrict__ out)
{
    __shared__ float s[CH][HALO_H][SPITCH];

    const int bx0 = blockIdx.x * TW;
    const int by0 = blockIdx.y * TH;
    const int b   = blockIdx.z;
    const int tx  = threadIdx.x;          // pixel cols bx0+2tx, bx0+2tx+1
    const int ty  = threadIdx.y;          // output rows by0+4ty .. +3
    const int tid = ty * 32 + tx;

    const float* __restrict__ xb = x + (size_t)b * CH * HW;

    // interior-x iff all 72 loaded cols (bx0-4 .. bx0+67) are in [0,511]
    const bool interior = (bx0 >= 4) && (bx0 + 68 <= WW);

    if (interior) {
        #pragma unroll
        for (int c = 0; c < CH; c++) {
            const float* __restrict__ xc = xb + c * HW;
            #pragma unroll 1
            for (int i = tid; i < HALO_H * (SPITCH / 4); i += 256) {   // 612
                int r = i / (SPITCH / 4);
                int g = i - r * (SPITCH / 4);                          // 0..17
                int gr = min(max(by0 - 1 + r, 0), HH - 1);
                float4 v = *(const float4*)(xc + (size_t)gr * WW + (bx0 - 4) + 4 * g);
                *(float4*)&s[c][r][4 * g] = v;
            }
        }
    } else {
        // x-edge blocks: scalar, replicate-clamped, cols j=2..69 (bx0-2..bx0+65)
        #pragma unroll
        for (int c = 0; c < CH; c++) {
            const float* __restrict__ xc = xb + c * HW;
            #pragma unroll 1
            for (int i = tid; i < HALO_H * 68; i += 256) {
                int r = i / 68;
                int j = i - r * 68 + 2;                                // 2..69
                int gr = min(max(by0 - 1 + r, 0), HH - 1);
                int gc = min(max(bx0 - 4 + j, 0), WW - 1);
                s[c][r][j] = __ldg(xc + (size_t)gr * WW + gc);
            }
        }
    }
    __syncthreads();

    const int r0 = ty * 4;   // first halo row of this thread's first window

    // Rolling 3-row window per channel:
    //   L=a[p-1], C0=a[p], C1=a[p+1], R=a[p+2], D0=a[p+1]-a[p-1], D1=a[p+2]-a[p]
    float L[CH][3], C0[CH][3], C1[CH][3], R[CH][3], D0[CH][3], D1[CH][3];

    #define LOADROW(c, hr, sl) do {                                    \
        float2 v0 = *(const float2*)&s[c][hr][2 * tx + 2];             \
        float2 v1 = *(const float2*)&s[c][hr][2 * tx + 4];             \
        float2 v2 = *(const float2*)&s[c][hr][2 * tx + 6];             \
        L[c][sl]  = v0.y; C0[c][sl] = v1.x;                            \
        C1[c][sl] = v1.y; R[c][sl]  = v2.x;                            \
        D0[c][sl] = v1.y - v0.y;   /* a[p+1]-a[p-1] */                 \
        D1[c][sl] = v2.x - v1.x;   /* a[p+2]-a[p]   */ } while (0)

    #pragma unroll
    for (int c = 0; c < CH; c++) {
        LOADROW(c, r0,     0);
        LOADROW(c, r0 + 1, 1);
    }

    const size_t obase = (size_t)b * HW + (size_t)(by0 + r0) * WW + (bx0 + 2 * tx);
    const size_t oang  = (size_t)BATCH * HW;

    #pragma unroll
    for (int k = 0; k < 4; k++) {
        const int s0 = k % 3, s1 = (k + 1) % 3, s2 = (k + 2) % 3;

        #pragma unroll
        for (int c = 0; c < CH; c++) {
            LOADROW(c, r0 + k + 2, s2);
        }

        float bgx0 = 0.f, bgy0 = 0.f, bm0 = -1.f;
        float bgx1 = 0.f, bgy1 = 0.f, bm1 = -1.f;

        #pragma unroll
        for (int c = 0; c < CH; c++) {
            // pixel 0 (col p): identical fp expressions to R1/R2
            float gx0 = (D0[c][s0] + 2.0f * D0[c][s1] + D0[c][s2]) * 0.125f;
            float gy0 = ((L[c][s2]  - L[c][s0])
                       + 2.0f * (C0[c][s2] - C0[c][s0])
                       + (C1[c][s2] - C1[c][s0])) * 0.125f;
            float m0 = gx0 * gx0 + gy0 * gy0 + 1e-9f;
            if (m0 > bm0) { bm0 = m0; bgx0 = gx0; bgy0 = gy0; }

            // pixel 1 (col p+1)
            float gx1 = (D1[c][s0] + 2.0f * D1[c][s1] + D1[c][s2]) * 0.125f;
            float gy1 = ((C0[c][s2] - C0[c][s0])
                       + 2.0f * (C1[c][s2] - C1[c][s0])
                       + (R[c][s2]  - R[c][s0])) * 0.125f;
            float m1 = gx1 * gx1 + gy1 * gy1 + 1e-9f;
            if (m1 > bm1) { bm1 = m1; bgx1 = gx1; bgy1 = gy1; }
        }

        float mag0 = sqrtf(bm0);
        float mag1 = sqrtf(bm1);

        float ytr0 = (bgy0 == 0.0f) ? 1e-9f : bgy0;
        float ytr1 = (bgy1 == 0.0f) ? 1e-9f : bgy1;
        float ang0 = fminf(fmaxf(__fdividef(bgx0, ytr0), -10.0f), 10.0f);
        float ang1 = fminf(fmaxf(__fdividef(bgx1, ytr1), -10.0f), 10.0f);

        const size_t o = obase + (size_t)k * WW;
        *(float2*)&out[o]        = make_float2(mag0, mag1);
        *(float2*)&out[oang + o] = make_float2(ang0, ang1);
    }
    #undef LOADROW
}

extern "C" void kernel_launch(void* const* d_in, const int* in_sizes, int n_in,
                              void* d_out, int out_size)
{
    const float* x = (const float*)d_in[0];
    float* out = (float*)d_out;

    dim3 block(32, 8, 1);
    dim3 grid(WW / TW, HH / TH, BATCH);   // (8, 16, 16) = 2048 blocks
    sobel_kernel<<<grid, block>>>(x, out);
}

// round 5
// speedup vs baseline: 1.5127x; 1.0580x over previous
#include <cuda_runtime.h>

// Sobel_16724602651101 — R4
// x: (16, 3, 512, 512) fp32 -> out: [magnitude | angle] each (16,512,512) fp32.
//
// 64x16 tiles, 2px x 2rows per thread, channel-sequential 4-row window,
// occupancy-first (<=42 regs). gx/gy/argmax expressions bitwise identical to
// R1 (matched XLA at 1.06e-7); final sqrt uses MUFU approx (<=2 ulp).

#define BATCH 16
#define CH 3
#define HH 512
#define WW 512
#define HW (HH * WW)

#define TW 64            // tile width  (output)
#define TH 16            // tile height (output)
#define HALO_H (TH + 2)  // 18 halo rows
#define SPITCH 72        // smem row pitch; local col j = globalcol - (bx0-4)

__device__ __forceinline__ float fsqrt_approx(float a)
{
    float r;
    asm("sqrt.approx.f32 %0, %1;" : "=f"(r) : "f"(a));
    return r;
}

__global__ __launch_bounds__(256, 6)
void sobel_kernel(const float* __restrict__ x, float* __restrict__ out)
{
    __shared__ float s[CH][HALO_H][SPITCH];

    const int bx0 = blockIdx.x * TW;
    const int by0 = blockIdx.y * TH;
    const int b   = blockIdx.z;
    const int tx  = threadIdx.x;          // pixel cols bx0+2tx, bx0+2tx+1
    const int ty  = threadIdx.y;          // output rows by0+2ty, by0+2ty+1
    const int tid = ty * 32 + tx;

    const float* __restrict__ xb = x + (size_t)b * CH * HW;

    // interior-x iff all 72 loaded cols (bx0-4 .. bx0+67) are in [0,511]
    const bool interior = (bx0 >= 4) && (bx0 + 68 <= WW);

    if (interior) {
        #pragma unroll
        for (int c = 0; c < CH; c++) {
            const float* __restrict__ xc = xb + c * HW;
            #pragma unroll 1
            for (int i = tid; i < HALO_H * (SPITCH / 4); i += 256) {   // 324
                int r = i / (SPITCH / 4);
                int g = i - r * (SPITCH / 4);                          // 0..17
                int gr = min(max(by0 - 1 + r, 0), HH - 1);
                float4 v = *(const float4*)(xc + (size_t)gr * WW + (bx0 - 4) + 4 * g);
                *(float4*)&s[c][r][4 * g] = v;
            }
        }
    } else {
        // x-edge blocks: scalar, replicate-clamped, cols j=2..69
        #pragma unroll
        for (int c = 0; c < CH; c++) {
            const float* __restrict__ xc = xb + c * HW;
            #pragma unroll 1
            for (int i = tid; i < HALO_H * 68; i += 256) {
                int r = i / 68;
                int j = i - r * 68 + 2;                                // 2..69
                int gr = min(max(by0 - 1 + r, 0), HH - 1);
                int gc = min(max(bx0 - 4 + j, 0), WW - 1);
                s[c][r][j] = __ldg(xc + (size_t)gr * WW + gc);
            }
        }
    }
    __syncthreads();

    const int r0 = 2 * ty;   // halo rows r0 .. r0+3 feed output rows r0, r0+1

    // accumulators: [row][pixel]
    float bm[2][2], bgx[2][2], bgy[2][2];
    #pragma unroll
    for (int rr = 0; rr < 2; rr++)
        #pragma unroll
        for (int p = 0; p < 2; p++) { bm[rr][p] = -1.f; bgx[rr][p] = 0.f; bgy[rr][p] = 0.f; }

    #pragma unroll
    for (int c = 0; c < CH; c++) {
        // 4-row window for this channel: cols p-1, p, p+1, p+2
        float Lr[4], M0[4], M1[4], Rr[4];
        #pragma unroll
        for (int i = 0; i < 4; i++) {
            float2 v0 = *(const float2*)&s[c][r0 + i][2 * tx + 2];
            float2 v1 = *(const float2*)&s[c][r0 + i][2 * tx + 4];
            float  w  = s[c][r0 + i][2 * tx + 6];
            Lr[i] = v0.y; M0[i] = v1.x; M1[i] = v1.y; Rr[i] = w;
        }

        #pragma unroll
        for (int rr = 0; rr < 2; rr++) {
            const int t = rr, m = rr + 1, bo = rr + 2;

            // pixel 0 — expressions identical to R1
            float gx0 = ((M1[t] - Lr[t]) + 2.0f * (M1[m] - Lr[m]) + (M1[bo] - Lr[bo])) * 0.125f;
            float gy0 = ((Lr[bo] - Lr[t]) + 2.0f * (M0[bo] - M0[t]) + (M1[bo] - M1[t])) * 0.125f;
            float m0 = gx0 * gx0 + gy0 * gy0 + 1e-9f;
            if (m0 > bm[rr][0]) { bm[rr][0] = m0; bgx[rr][0] = gx0; bgy[rr][0] = gy0; }

            // pixel 1
            float gx1 = ((Rr[t] - M0[t]) + 2.0f * (Rr[m] - M0[m]) + (Rr[bo] - M0[bo])) * 0.125f;
            float gy1 = ((M0[bo] - M0[t]) + 2.0f * (M1[bo] - M1[t]) + (Rr[bo] - Rr[t])) * 0.125f;
            float m1 = gx1 * gx1 + gy1 * gy1 + 1e-9f;
            if (m1 > bm[rr][1]) { bm[rr][1] = m1; bgx[rr][1] = gx1; bgy[rr][1] = gy1; }
        }
    }

    const size_t oang = (size_t)BATCH * HW;

    #pragma unroll
    for (int rr = 0; rr < 2; rr++) {
        float mag0 = fsqrt_approx(bm[rr][0]);
        float mag1 = fsqrt_approx(bm[rr][1]);

        float ytr0 = (bgy[rr][0] == 0.0f) ? 1e-9f : bgy[rr][0];
        float ytr1 = (bgy[rr][1] == 0.0f) ? 1e-9f : bgy[rr][1];
        float ang0 = fminf(fmaxf(__fdividef(bgx[rr][0], ytr0), -10.0f), 10.0f);
        float ang1 = fminf(fmaxf(__fdividef(bgx[rr][1], ytr1), -10.0f), 10.0f);

        const size_t o = (size_t)b * HW + (size_t)(by0 + r0 + rr) * WW + (bx0 + 2 * tx);
        *(float2*)&out[o]        = make_float2(mag0, mag1);
        *(float2*)&out[oang + o] = make_float2(ang0, ang1);
    }
}

extern "C" void kernel_launch(void* const* d_in, const int* in_sizes, int n_in,
                              void* d_out, int out_size)
{
    const float* x = (const float*)d_in[0];
    float* out = (float*)d_out;

    dim3 block(32, 8, 1);
    dim3 grid(WW / TW, HH / TH, BATCH);   // (8, 32, 16) = 4096 blocks
    sobel_kernel<<<grid, block>>>(x, out);
}

// round 6
// speedup vs baseline: 1.5473x; 1.0229x over previous
#include <cuda_runtime.h>

// Sobel_16724602651101 — R5
// x: (16, 3, 512, 512) fp32 -> out: [magnitude | angle] each (16,512,512) fp32.
//
// No shared memory, no barrier: each thread computes 4 consecutive pixels of
// one row. 1x LDG.128 per (row,channel) + warp shuffles for the halo columns;
// replicate padding via clamped row/col indices. Vertical reuse via L1/L2.
// gx/gy/argmax expressions bitwise identical to R1 (matched XLA at 1.06e-7);
// final sqrt = MUFU approx, angle div = __fdividef (clipped to +-10).

#define BATCH 16
#define CH 3
#define HH 512
#define WW 512
#define HW (HH * WW)

#define FULLMASK 0xFFFFFFFFu

__device__ __forceinline__ float fsqrt_approx(float a)
{
    float r;
    asm("sqrt.approx.f32 %0, %1;" : "=f"(r) : "f"(a));
    return r;
}

__global__ __launch_bounds__(256, 5)
void sobel_kernel(const float* __restrict__ x, float* __restrict__ out)
{
    const int lane = threadIdx.x;                    // 0..31
    const int y    = blockIdx.y * 8 + threadIdx.y;   // output row
    const int b    = blockIdx.z;
    const int c0   = blockIdx.x * 128 + lane * 4;    // first of 4 pixel cols (16B aligned)

    const float* __restrict__ xb = x + (size_t)b * CH * HW;

    const size_t roff[3] = {
        (size_t)max(y - 1, 0) * WW,
        (size_t)y * WW,
        (size_t)min(y + 1, HH - 1) * WW
    };
    const int cl = max(c0 - 1, 0);        // left halo col (lane 0 patch)
    const int cr = min(c0 + 4, WW - 1);   // right halo col (lane 31 patch)

    float bm[4], bgx[4], bgy[4];
    #pragma unroll
    for (int p = 0; p < 4; p++) { bm[p] = -1.f; bgx[p] = 0.f; bgy[p] = 0.f; }

    #pragma unroll
    for (int c = 0; c < CH; c++) {
        const float* __restrict__ xc = xb + (size_t)c * HW;

        // 3 rows x 6 cols window: w[i][0..5] = cols c0-1 .. c0+4
        float w[3][6];
        #pragma unroll
        for (int i = 0; i < 3; i++) {
            const float* __restrict__ rp = xc + roff[i];
            float4 v = __ldg((const float4*)(rp + c0));
            float lf = __shfl_up_sync(FULLMASK, v.w, 1);
            float rt = __shfl_down_sync(FULLMASK, v.x, 1);
            if (lane == 0)  lf = __ldg(rp + cl);
            if (lane == 31) rt = __ldg(rp + cr);
            w[i][0] = lf;  w[i][1] = v.x; w[i][2] = v.y;
            w[i][3] = v.z; w[i][4] = v.w; w[i][5] = rt;
        }

        #pragma unroll
        for (int p = 0; p < 4; p++) {
            float a00 = w[0][p], a01 = w[0][p + 1], a02 = w[0][p + 2];
            float a10 = w[1][p],                    a12 = w[1][p + 2];
            float a20 = w[2][p], a21 = w[2][p + 1], a22 = w[2][p + 2];

            // identical fp expressions to R1 (proven XLA match)
            float gx = ((a02 - a00) + 2.0f * (a12 - a10) + (a22 - a20)) * 0.125f;
            float gy = ((a20 - a00) + 2.0f * (a21 - a01) + (a22 - a02)) * 0.125f;
            float m  = gx * gx + gy * gy + 1e-9f;

            if (m > bm[p]) { bm[p] = m; bgx[p] = gx; bgy[p] = gy; }
        }
    }

    float4 mag, ang;
    {
        mag.x = fsqrt_approx(bm[0]); mag.y = fsqrt_approx(bm[1]);
        mag.z = fsqrt_approx(bm[2]); mag.w = fsqrt_approx(bm[3]);

        float y0 = (bgy[0] == 0.f) ? 1e-9f : bgy[0];
        float y1 = (bgy[1] == 0.f) ? 1e-9f : bgy[1];
        float y2 = (bgy[2] == 0.f) ? 1e-9f : bgy[2];
        float y3 = (bgy[3] == 0.f) ? 1e-9f : bgy[3];
        ang.x = fminf(fmaxf(__fdividef(bgx[0], y0), -10.f), 10.f);
        ang.y = fminf(fmaxf(__fdividef(bgx[1], y1), -10.f), 10.f);
        ang.z = fminf(fmaxf(__fdividef(bgx[2], y2), -10.f), 10.f);
        ang.w = fminf(fmaxf(__fdividef(bgx[3], y3), -10.f), 10.f);
    }

    const size_t o = (size_t)b * HW + (size_t)y * WW + c0;
    *(float4*)&out[o]                      = mag;
    *(float4*)&out[(size_t)BATCH * HW + o] = ang;
}

extern "C" void kernel_launch(void* const* d_in, const int* in_sizes, int n_in,
                              void* d_out, int out_size)
{
    const float* x = (const float*)d_in[0];
    float* out = (float*)d_out;

    dim3 block(32, 8, 1);                 // warp = 128-col strip, 8 rows/block
    dim3 grid(WW / 128, HH / 8, BATCH);   // (4, 64, 16) = 4096 blocks
    sobel_kernel<<<grid, block>>>(x, out);
}